// round 1
// baseline (speedup 1.0000x reference)
#include <cuda_runtime.h>
#include <math.h>

#define B_    2
#define HW_   4096
#define C_    512
#define TOK_  8192          // B_*HW_
#define G_    32
#define CPG_  16            // C_/G_
#define EPS_  1e-5f
#define SCALE_ 0.04419417382415922f   // 1/sqrt(512)

// ---------------- scratch (device globals; no allocation allowed) ----------
__device__ float g_h[TOK_ * C_];
__device__ float g_q[TOK_ * C_];
__device__ float g_k[TOK_ * C_];
__device__ float g_v[TOK_ * C_];
__device__ float g_o[TOK_ * C_];
__device__ float g_s[(size_t)B_ * HW_ * HW_];   // 128 MB attention scores
__device__ float g_mean[B_ * G_];
__device__ float g_rstd[B_ * G_];

// ---------------- GroupNorm stats: one block per (batch, group) ------------
__global__ void gn_stats(const float* __restrict__ x) {
    int bg = blockIdx.x;
    int b = bg / G_, g = bg % G_;
    const float* base = x + (size_t)b * HW_ * C_ + g * CPG_;
    float s = 0.f, s2 = 0.f;
    for (int p = threadIdx.x; p < HW_; p += blockDim.x) {
        const float* px = base + (size_t)p * C_;
        #pragma unroll
        for (int c = 0; c < CPG_; c += 4) {
            float4 v = *(const float4*)(px + c);
            s  += v.x + v.y + v.z + v.w;
            s2 += v.x*v.x + v.y*v.y + v.z*v.z + v.w*v.w;
        }
    }
    __shared__ float sh[256], sh2[256];
    sh[threadIdx.x] = s; sh2[threadIdx.x] = s2;
    __syncthreads();
    for (int o = 128; o > 0; o >>= 1) {
        if (threadIdx.x < o) {
            sh[threadIdx.x]  += sh[threadIdx.x + o];
            sh2[threadIdx.x] += sh2[threadIdx.x + o];
        }
        __syncthreads();
    }
    if (threadIdx.x == 0) {
        const float inv_n = 1.f / (float)(HW_ * CPG_);
        float m = sh[0] * inv_n;
        float var = sh2[0] * inv_n - m * m;
        g_mean[bg] = m;
        g_rstd[bg] = rsqrtf(var + EPS_);
    }
}

// ---------------- GroupNorm apply (elementwise, float4) --------------------
__global__ void gn_apply(const float* __restrict__ x,
                         const float* __restrict__ gamma,
                         const float* __restrict__ beta) {
    size_t i = ((size_t)blockIdx.x * blockDim.x + threadIdx.x) * 4;
    if (i >= (size_t)TOK_ * C_) return;
    int c = (int)(i % C_);
    int b = (int)(i / ((size_t)HW_ * C_));
    int bg = b * G_ + c / CPG_;
    float m = g_mean[bg], r = g_rstd[bg];
    float4 xv = *(const float4*)(x + i);
    float4 gv = *(const float4*)(gamma + c);
    float4 bv = *(const float4*)(beta + c);
    float4 o;
    o.x = (xv.x - m) * r * gv.x + bv.x;
    o.y = (xv.y - m) * r * gv.y + bv.y;
    o.z = (xv.z - m) * r * gv.z + bv.z;
    o.w = (xv.w - m) * r * gv.w + bv.w;
    *(float4*)(g_h + i) = o;
}

// ---------------- SGEMM NN: C = alpha*A@B (+bias) (+res) -------------------
// A [M,K] rm, B [K,N] rm. 128x128x16 tile, 256 threads, 8x8 microtile.
__global__ __launch_bounds__(256)
void sgemm_nn(const float* __restrict__ A, const float* __restrict__ Bm,
              const float* __restrict__ bias, const float* __restrict__ res,
              float* __restrict__ C,
              int M, int N, int K, long sA, long sB, long sC, float alpha) {
    A  += (long)blockIdx.z * sA;
    Bm += (long)blockIdx.z * sB;
    C  += (long)blockIdx.z * sC;
    const float* R = res ? res + (long)blockIdx.z * sC : nullptr;

    __shared__ float As[16][128];
    __shared__ float Bs[16][128];

    int tid = threadIdx.x;
    int tm = (tid >> 4) << 3;      // 0..120 step 8
    int tn = (tid & 15) << 3;
    int ar = tid >> 2, ac = (tid & 3) << 2;      // A tile load idx
    int br = tid >> 5, bc = (tid & 31) << 2;     // B tile load idx
    int m0 = blockIdx.y * 128, n0 = blockIdx.x * 128;

    float acc[8][8] = {};

    for (int k0 = 0; k0 < K; k0 += 16) {
        float4 av0 = *(const float4*)(A + (long)(m0 + ar)      * K + k0 + ac);
        float4 av1 = *(const float4*)(A + (long)(m0 + ar + 64) * K + k0 + ac);
        float4 bv0 = *(const float4*)(Bm + (long)(k0 + br)     * N + n0 + bc);
        float4 bv1 = *(const float4*)(Bm + (long)(k0 + br + 8) * N + n0 + bc);
        __syncthreads();
        As[ac + 0][ar] = av0.x; As[ac + 1][ar] = av0.y;
        As[ac + 2][ar] = av0.z; As[ac + 3][ar] = av0.w;
        As[ac + 0][ar + 64] = av1.x; As[ac + 1][ar + 64] = av1.y;
        As[ac + 2][ar + 64] = av1.z; As[ac + 3][ar + 64] = av1.w;
        *(float4*)(&Bs[br][bc])     = bv0;
        *(float4*)(&Bs[br + 8][bc]) = bv1;
        __syncthreads();
        #pragma unroll
        for (int k = 0; k < 16; k++) {
            float4 a0 = *(const float4*)&As[k][tm];
            float4 a1 = *(const float4*)&As[k][tm + 4];
            float4 b0 = *(const float4*)&Bs[k][tn];
            float4 b1 = *(const float4*)&Bs[k][tn + 4];
            float a[8] = {a0.x, a0.y, a0.z, a0.w, a1.x, a1.y, a1.z, a1.w};
            float b[8] = {b0.x, b0.y, b0.z, b0.w, b1.x, b1.y, b1.z, b1.w};
            #pragma unroll
            for (int i = 0; i < 8; i++)
                #pragma unroll
                for (int j = 0; j < 8; j++)
                    acc[i][j] += a[i] * b[j];
        }
    }

    #pragma unroll
    for (int i = 0; i < 8; i++) {
        long off = (long)(m0 + tm + i) * N + n0 + tn;
        #pragma unroll
        for (int j = 0; j < 8; j += 4) {
            float4 c;
            c.x = acc[i][j + 0] * alpha;
            c.y = acc[i][j + 1] * alpha;
            c.z = acc[i][j + 2] * alpha;
            c.w = acc[i][j + 3] * alpha;
            if (bias) {
                float4 bb = *(const float4*)(bias + n0 + tn + j);
                c.x += bb.x; c.y += bb.y; c.z += bb.z; c.w += bb.w;
            }
            if (R) {
                float4 r = *(const float4*)(R + off + j);
                c.x += r.x; c.y += r.y; c.z += r.z; c.w += r.w;
            }
            *(float4*)(C + off + j) = c;
        }
    }
}

// ---------------- SGEMM NT: C = alpha * A @ B^T ----------------------------
// A [M,K] rm, B [N,K] rm.
__global__ __launch_bounds__(256)
void sgemm_nt(const float* __restrict__ A, const float* __restrict__ Bm,
              float* __restrict__ C,
              int M, int N, int K, long sA, long sB, long sC, float alpha) {
    A  += (long)blockIdx.z * sA;
    Bm += (long)blockIdx.z * sB;
    C  += (long)blockIdx.z * sC;

    __shared__ float As[16][128];
    __shared__ float Bs[16][128];

    int tid = threadIdx.x;
    int tm = (tid >> 4) << 3;
    int tn = (tid & 15) << 3;
    int ar = tid >> 2, ac = (tid & 3) << 2;
    int m0 = blockIdx.y * 128, n0 = blockIdx.x * 128;

    float acc[8][8] = {};

    for (int k0 = 0; k0 < K; k0 += 16) {
        float4 av0 = *(const float4*)(A + (long)(m0 + ar)      * K + k0 + ac);
        float4 av1 = *(const float4*)(A + (long)(m0 + ar + 64) * K + k0 + ac);
        float4 bv0 = *(const float4*)(Bm + (long)(n0 + ar)      * K + k0 + ac);
        float4 bv1 = *(const float4*)(Bm + (long)(n0 + ar + 64) * K + k0 + ac);
        __syncthreads();
        As[ac + 0][ar] = av0.x; As[ac + 1][ar] = av0.y;
        As[ac + 2][ar] = av0.z; As[ac + 3][ar] = av0.w;
        As[ac + 0][ar + 64] = av1.x; As[ac + 1][ar + 64] = av1.y;
        As[ac + 2][ar + 64] = av1.z; As[ac + 3][ar + 64] = av1.w;
        Bs[ac + 0][ar] = bv0.x; Bs[ac + 1][ar] = bv0.y;
        Bs[ac + 2][ar] = bv0.z; Bs[ac + 3][ar] = bv0.w;
        Bs[ac + 0][ar + 64] = bv1.x; Bs[ac + 1][ar + 64] = bv1.y;
        Bs[ac + 2][ar + 64] = bv1.z; Bs[ac + 3][ar + 64] = bv1.w;
        __syncthreads();
        #pragma unroll
        for (int k = 0; k < 16; k++) {
            float4 a0 = *(const float4*)&As[k][tm];
            float4 a1 = *(const float4*)&As[k][tm + 4];
            float4 b0 = *(const float4*)&Bs[k][tn];
            float4 b1 = *(const float4*)&Bs[k][tn + 4];
            float a[8] = {a0.x, a0.y, a0.z, a0.w, a1.x, a1.y, a1.z, a1.w};
            float b[8] = {b0.x, b0.y, b0.z, b0.w, b1.x, b1.y, b1.z, b1.w};
            #pragma unroll
            for (int i = 0; i < 8; i++)
                #pragma unroll
                for (int j = 0; j < 8; j++)
                    acc[i][j] += a[i] * b[j];
        }
    }

    #pragma unroll
    for (int i = 0; i < 8; i++) {
        long off = (long)(m0 + tm + i) * N + n0 + tn;
        #pragma unroll
        for (int j = 0; j < 8; j += 4) {
            float4 c;
            c.x = acc[i][j + 0] * alpha;
            c.y = acc[i][j + 1] * alpha;
            c.z = acc[i][j + 2] * alpha;
            c.w = acc[i][j + 3] * alpha;
            *(float4*)(C + off + j) = c;
        }
    }
}

// ---------------- row softmax over 4096 columns ----------------------------
__global__ void softmax_rows(float* __restrict__ S) {
    float* p = S + (size_t)blockIdx.x * HW_;
    int t = threadIdx.x;
    __shared__ float red[256];

    float mx = -1e30f;
    for (int j = t * 4; j < HW_; j += 256 * 4) {
        float4 v = *(const float4*)(p + j);
        mx = fmaxf(mx, fmaxf(fmaxf(v.x, v.y), fmaxf(v.z, v.w)));
    }
    red[t] = mx; __syncthreads();
    for (int o = 128; o > 0; o >>= 1) {
        if (t < o) red[t] = fmaxf(red[t], red[t + o]);
        __syncthreads();
    }
    mx = red[0]; __syncthreads();

    float sum = 0.f;
    for (int j = t * 4; j < HW_; j += 256 * 4) {
        float4 v = *(const float4*)(p + j);
        v.x = __expf(v.x - mx); v.y = __expf(v.y - mx);
        v.z = __expf(v.z - mx); v.w = __expf(v.w - mx);
        sum += v.x + v.y + v.z + v.w;
        *(float4*)(p + j) = v;
    }
    red[t] = sum; __syncthreads();
    for (int o = 128; o > 0; o >>= 1) {
        if (t < o) red[t] += red[t + o];
        __syncthreads();
    }
    float inv = 1.f / red[0];

    for (int j = t * 4; j < HW_; j += 256 * 4) {
        float4 v = *(const float4*)(p + j);
        v.x *= inv; v.y *= inv; v.z *= inv; v.w *= inv;
        *(float4*)(p + j) = v;
    }
}

// ---------------- launch ---------------------------------------------------
extern "C" void kernel_launch(void* const* d_in, const int* in_sizes, int n_in,
                              void* d_out, int out_size) {
    const float* x     = (const float*)d_in[0];
    const float* gamma = (const float*)d_in[1];
    const float* beta  = (const float*)d_in[2];
    const float* wq    = (const float*)d_in[3];
    const float* bq    = (const float*)d_in[4];
    const float* wk    = (const float*)d_in[5];
    const float* bk    = (const float*)d_in[6];
    const float* wv    = (const float*)d_in[7];
    const float* bv    = (const float*)d_in[8];
    const float* wp    = (const float*)d_in[9];
    const float* bp    = (const float*)d_in[10];
    float* out = (float*)d_out;

    float *h, *q, *k, *v, *o, *s;
    cudaGetSymbolAddress((void**)&h, g_h);
    cudaGetSymbolAddress((void**)&q, g_q);
    cudaGetSymbolAddress((void**)&k, g_k);
    cudaGetSymbolAddress((void**)&v, g_v);
    cudaGetSymbolAddress((void**)&o, g_o);
    cudaGetSymbolAddress((void**)&s, g_s);

    const long sQK = (long)HW_ * C_;          // per-batch stride of q/k/v/o
    const long sS  = (long)HW_ * HW_;         // per-batch stride of scores

    // 1) GroupNorm
    gn_stats<<<B_ * G_, 256>>>(x);
    gn_apply<<<(TOK_ * C_ / 4 + 255) / 256, 256>>>(x, gamma, beta);

    // 2) Q, K, V projections: [8192,512] @ [512,512]
    sgemm_nn<<<dim3(4, 64, 1), 256>>>(h, wq, bq, nullptr, q, TOK_, C_, C_, 0, 0, 0, 1.f);
    sgemm_nn<<<dim3(4, 64, 1), 256>>>(h, wk, bk, nullptr, k, TOK_, C_, C_, 0, 0, 0, 1.f);
    sgemm_nn<<<dim3(4, 64, 1), 256>>>(h, wv, bv, nullptr, v, TOK_, C_, C_, 0, 0, 0, 1.f);

    // 3) S = scale * Q @ K^T  (per batch: 4096x4096x512)
    sgemm_nt<<<dim3(32, 32, B_), 256>>>(q, k, s, HW_, HW_, C_, sQK, sQK, sS, SCALE_);

    // 4) softmax rows
    softmax_rows<<<B_ * HW_, 256>>>(s);

    // 5) O = P @ V  (per batch: 4096x512x4096)
    sgemm_nn<<<dim3(4, 32, B_), 256>>>(s, v, nullptr, nullptr, o, HW_, C_, HW_, sS, sQK, sQK, 1.f);

    // 6) out = x + O @ Wp + bp
    sgemm_nn<<<dim3(4, 64, 1), 256>>>(o, wp, bp, x, out, TOK_, C_, C_, 0, 0, 0, 1.f);
}

// round 3
// speedup vs baseline: 2.8193x; 2.8193x over previous
#include <cuda_runtime.h>
#include <cstdint>
#include <math.h>

#define B_    2
#define HW_   4096
#define C_    512
#define TOK_  8192
#define G_    32
#define CPG_  16
#define EPS_  1e-5f
#define SCALE_ 0.04419417382415922f   // 1/sqrt(512)

// ---------------- scratch (device globals) ---------------------------------
__device__ float g_h[TOK_ * C_];
__device__ float g_q[TOK_ * C_];
__device__ float g_k[TOK_ * C_];
__device__ float g_v[TOK_ * C_];
__device__ float g_o[TOK_ * C_];
__device__ float g_w[4 * C_ * C_];                // tf32-rounded weights
__device__ float g_s[(size_t)B_ * HW_ * HW_];     // scores / probs
__device__ float2 g_part[B_ * G_][8];
__device__ float g_mean[B_ * G_];
__device__ float g_rstd[B_ * G_];

// ---------------- helpers ---------------------------------------------------
__device__ __forceinline__ float tf32r(float x) {
    float y;
    asm("cvt.rna.tf32.f32 %0, %1;" : "=f"(y) : "f"(x));
    return y;
}
__device__ __forceinline__ uint32_t smem_u32(const void* p) {
    uint32_t a;
    asm("{ .reg .u64 t; cvta.to.shared.u64 t, %1; cvt.u32.u64 %0, t; }" : "=r"(a) : "l"(p));
    return a;
}
__device__ __forceinline__ void cp16(uint32_t dst, const void* src) {
    asm volatile("cp.async.ca.shared.global [%0], [%1], 16;" :: "r"(dst), "l"(src));
}
__device__ __forceinline__ void cp_commit() {
    asm volatile("cp.async.commit_group;");
}
__device__ __forceinline__ void cp_wait2() {
    asm volatile("cp.async.wait_group 2;" ::: "memory");
}
// m16n8k8 tf32 mma, acc in-place
__device__ __forceinline__ void mma8(float* d, const uint32_t* a, const uint32_t* b) {
    asm volatile(
        "mma.sync.aligned.m16n8k8.row.col.f32.tf32.tf32.f32 "
        "{%0,%1,%2,%3}, {%4,%5,%6,%7}, {%8,%9}, {%0,%1,%2,%3};"
        : "+f"(d[0]), "+f"(d[1]), "+f"(d[2]), "+f"(d[3])
        : "r"(a[0]), "r"(a[1]), "r"(a[2]), "r"(a[3]), "r"(b[0]), "r"(b[1]));
}

#define STAGE_F  5120                 // floats per stage (A 2560 + B 2560)
#define SMEM_BYTES (4 * STAGE_F * 4)  // 81920

// ---------------- tf32 tensor-core GEMM -------------------------------------
// C = alpha * A @ op(B) (+bias)(+res).  A [M,K] row-major.
// BT=true : B [N,K] row-major (C = A@B^T).  BT=false: B [K,N] row-major (C = A@B).
// RND: round outputs to tf32 (for tensors feeding later GEMMs).
template <bool BT, bool RND>
__global__ __launch_bounds__(256, 2)
void mma_gemm(const float* __restrict__ A, const float* __restrict__ Bm,
              const float* __restrict__ bias, const float* __restrict__ res,
              float* __restrict__ Cc,
              int M, int N, int K, long sA, long sB, long sC, float alpha) {
    extern __shared__ float sm[];
    A  += (long)blockIdx.z * sA;
    Bm += (long)blockIdx.z * sB;
    Cc += (long)blockIdx.z * sC;
    const float* R = res ? res + (long)blockIdx.z * sC : nullptr;

    const int tid = threadIdx.x;
    const int lane = tid & 31, w = tid >> 5;
    const int gid = lane >> 2, tig = lane & 3;
    const int m0 = blockIdx.y * 128, n0 = blockIdx.x * 128;
    const int wm = (w >> 2) * 64, wn = (w & 3) * 32;
    const uint32_t sb = smem_u32(sm);
    const int NKB = K >> 4;

    // --- stage loader: chunk kb -> stage st ---------------------------------
    auto stage_load = [&](int st, int kb) {
        const uint32_t abase = sb + (uint32_t)st * STAGE_F * 4;
        const uint32_t bbase = abase + 2560 * 4;
        const long k0 = (long)kb * 16;
        #pragma unroll
        for (int t = 0; t < 2; t++) {
            int c = tid + t * 256;
            int row = c >> 2, kq = c & 3;
            cp16(abase + (uint32_t)(row * 20 + kq * 4) * 4,
                 A + (long)(m0 + row) * K + k0 + kq * 4);
        }
        if (BT) {
            #pragma unroll
            for (int t = 0; t < 2; t++) {
                int c = tid + t * 256;
                int row = c >> 2, kq = c & 3;
                cp16(bbase + (uint32_t)(row * 20 + kq * 4) * 4,
                     Bm + (long)(n0 + row) * K + k0 + kq * 4);
            }
        } else {
            #pragma unroll
            for (int t = 0; t < 2; t++) {
                int c = tid + t * 256;
                int kk = c >> 5, nq = c & 31;
                cp16(bbase + (uint32_t)(kk * 136 + nq * 4) * 4,
                     Bm + (k0 + kk) * (long)N + n0 + nq * 4);
            }
        }
    };

    float acc[4][4][4] = {};

    stage_load(0, 0); cp_commit();
    stage_load(1, NKB > 1 ? 1 : 0); cp_commit();
    stage_load(2, NKB > 2 ? 2 : NKB - 1); cp_commit();

    for (int kb = 0; kb < NKB; kb++) {
        cp_wait2();
        __syncthreads();
        int nk = kb + 3; if (nk >= NKB) nk = NKB - 1;
        stage_load((kb + 3) & 3, nk); cp_commit();

        const float* As = sm + (kb & 3) * STAGE_F;
        const float* Bs = As + 2560;
        #pragma unroll
        for (int s = 0; s < 2; s++) {
            const int ks = s * 8 + tig;
            uint32_t a[4][4], b[4][2];
            #pragma unroll
            for (int i = 0; i < 4; i++) {
                int r0 = (wm + 16 * i + gid) * 20 + ks;
                a[i][0] = __float_as_uint(As[r0]);
                a[i][2] = __float_as_uint(As[r0 + 4]);
                a[i][1] = __float_as_uint(As[r0 + 160]);
                a[i][3] = __float_as_uint(As[r0 + 164]);
            }
            #pragma unroll
            for (int j = 0; j < 4; j++) {
                if (BT) {
                    int rb = (wn + 8 * j + gid) * 20 + ks;
                    b[j][0] = __float_as_uint(Bs[rb]);
                    b[j][1] = __float_as_uint(Bs[rb + 4]);
                } else {
                    int cb = wn + 8 * j + gid;
                    b[j][0] = __float_as_uint(Bs[ks * 136 + cb]);
                    b[j][1] = __float_as_uint(Bs[(ks + 4) * 136 + cb]);
                }
            }
            #pragma unroll
            for (int i = 0; i < 4; i++)
                #pragma unroll
                for (int j = 0; j < 4; j++)
                    mma8(acc[i][j], a[i], b[j]);
        }
    }

    // --- epilogue: fragments straight to gmem -------------------------------
    #pragma unroll
    for (int i = 0; i < 4; i++) {
        #pragma unroll
        for (int j = 0; j < 4; j++) {
            const int m = m0 + wm + 16 * i + gid;
            const int n = n0 + wn + 8 * j + 2 * tig;
            float2 bv = make_float2(0.f, 0.f);
            if (bias) bv = *(const float2*)(bias + n);
            long o0 = (long)m * N + n;
            long o1 = (long)(m + 8) * N + n;
            float2 v0, v1;
            v0.x = acc[i][j][0] * alpha + bv.x;
            v0.y = acc[i][j][1] * alpha + bv.y;
            v1.x = acc[i][j][2] * alpha + bv.x;
            v1.y = acc[i][j][3] * alpha + bv.y;
            if (R) {
                float2 r0 = *(const float2*)(R + o0);
                float2 r1 = *(const float2*)(R + o1);
                v0.x += r0.x; v0.y += r0.y; v1.x += r1.x; v1.y += r1.y;
            }
            if (RND) {
                v0.x = tf32r(v0.x); v0.y = tf32r(v0.y);
                v1.x = tf32r(v1.x); v1.y = tf32r(v1.y);
            }
            *(float2*)(Cc + o0) = v0;
            *(float2*)(Cc + o1) = v1;
        }
    }
}

// ---------------- weight rounding: g_w[i] = tf32(W_i) ------------------------
__global__ void wround(const float* __restrict__ w0, const float* __restrict__ w1,
                       const float* __restrict__ w2, const float* __restrict__ w3) {
    const float* src = blockIdx.y == 0 ? w0 : blockIdx.y == 1 ? w1
                     : blockIdx.y == 2 ? w2 : w3;
    int i = (blockIdx.x * 256 + threadIdx.x) * 4;
    float4 v = *(const float4*)(src + i);
    v.x = tf32r(v.x); v.y = tf32r(v.y); v.z = tf32r(v.z); v.w = tf32r(v.w);
    *(float4*)(g_w + (size_t)blockIdx.y * C_ * C_ + i) = v;
}

// ---------------- GroupNorm: partial stats, reduce, apply --------------------
__global__ void gn_part(const float* __restrict__ x) {
    int bg = blockIdx.x;
    int b = bg >> 5, g = bg & 31;
    const float* base = x + (size_t)b * HW_ * C_ + g * CPG_;
    float s = 0.f, s2 = 0.f;
    for (int t = 0; t < 2; t++) {
        int p = blockIdx.y * 512 + t * 256 + threadIdx.x;
        const float* px = base + (size_t)p * C_;
        #pragma unroll
        for (int c = 0; c < CPG_; c += 4) {
            float4 v = *(const float4*)(px + c);
            s  += v.x + v.y + v.z + v.w;
            s2 += v.x*v.x + v.y*v.y + v.z*v.z + v.w*v.w;
        }
    }
    __shared__ float sh[256], sh2[256];
    sh[threadIdx.x] = s; sh2[threadIdx.x] = s2;
    __syncthreads();
    for (int o = 128; o > 0; o >>= 1) {
        if (threadIdx.x < o) { sh[threadIdx.x] += sh[threadIdx.x+o]; sh2[threadIdx.x] += sh2[threadIdx.x+o]; }
        __syncthreads();
    }
    if (threadIdx.x == 0) g_part[bg][blockIdx.y] = make_float2(sh[0], sh2[0]);
}

__global__ void gn_red() {
    int bg = threadIdx.x;
    float s = 0.f, s2 = 0.f;
    #pragma unroll
    for (int i = 0; i < 8; i++) { float2 p = g_part[bg][i]; s += p.x; s2 += p.y; }
    const float inv_n = 1.f / (float)(HW_ * CPG_);
    float m = s * inv_n;
    float var = s2 * inv_n - m * m;
    g_mean[bg] = m;
    g_rstd[bg] = rsqrtf(var + EPS_);
}

__global__ void gn_apply(const float* __restrict__ x, const float* __restrict__ gamma,
                         const float* __restrict__ beta) {
    size_t i = ((size_t)blockIdx.x * blockDim.x + threadIdx.x) * 4;
    int c = (int)(i % C_);
    int b = (int)(i / ((size_t)HW_ * C_));
    int bg = b * G_ + c / CPG_;
    float m = g_mean[bg], r = g_rstd[bg];
    float4 xv = *(const float4*)(x + i);
    float4 gv = *(const float4*)(gamma + c);
    float4 bv = *(const float4*)(beta + c);
    float4 o;
    o.x = tf32r((xv.x - m) * r * gv.x + bv.x);
    o.y = tf32r((xv.y - m) * r * gv.y + bv.y);
    o.z = tf32r((xv.z - m) * r * gv.z + bv.z);
    o.w = tf32r((xv.w - m) * r * gv.w + bv.w);
    *(float4*)(g_h + i) = o;
}

// ---------------- register-resident softmax (one row per block) --------------
__global__ __launch_bounds__(512)
void softmax_rows(float* __restrict__ S) {
    float* p = S + (size_t)blockIdx.x * HW_;
    const int t = threadIdx.x, lane = t & 31, w = t >> 5;
    __shared__ float red[16];

    float4 v0 = *(const float4*)(p + t * 8);
    float4 v1 = *(const float4*)(p + t * 8 + 4);

    float mx = fmaxf(fmaxf(fmaxf(v0.x, v0.y), fmaxf(v0.z, v0.w)),
                     fmaxf(fmaxf(v1.x, v1.y), fmaxf(v1.z, v1.w)));
    #pragma unroll
    for (int o = 16; o; o >>= 1) mx = fmaxf(mx, __shfl_xor_sync(~0u, mx, o));
    if (lane == 0) red[w] = mx;
    __syncthreads();
    if (w == 0) {
        float tmn = red[lane & 15];
        #pragma unroll
        for (int o = 8; o; o >>= 1) tmn = fmaxf(tmn, __shfl_xor_sync(~0u, tmn, o));
        if (lane == 0) red[0] = tmn;
    }
    __syncthreads();
    mx = red[0];
    __syncthreads();

    v0.x = __expf(v0.x - mx); v0.y = __expf(v0.y - mx);
    v0.z = __expf(v0.z - mx); v0.w = __expf(v0.w - mx);
    v1.x = __expf(v1.x - mx); v1.y = __expf(v1.y - mx);
    v1.z = __expf(v1.z - mx); v1.w = __expf(v1.w - mx);
    float sum = v0.x + v0.y + v0.z + v0.w + v1.x + v1.y + v1.z + v1.w;
    #pragma unroll
    for (int o = 16; o; o >>= 1) sum += __shfl_xor_sync(~0u, sum, o);
    if (lane == 0) red[w] = sum;
    __syncthreads();
    if (w == 0) {
        float ts = red[lane & 15];
        #pragma unroll
        for (int o = 8; o; o >>= 1) ts += __shfl_xor_sync(~0u, ts, o);
        if (lane == 0) red[0] = ts;
    }
    __syncthreads();
    const float inv = 1.f / red[0];

    v0.x = tf32r(v0.x * inv); v0.y = tf32r(v0.y * inv);
    v0.z = tf32r(v0.z * inv); v0.w = tf32r(v0.w * inv);
    v1.x = tf32r(v1.x * inv); v1.y = tf32r(v1.y * inv);
    v1.z = tf32r(v1.z * inv); v1.w = tf32r(v1.w * inv);
    *(float4*)(p + t * 8)     = v0;
    *(float4*)(p + t * 8 + 4) = v1;
}

// ---------------- launch -----------------------------------------------------
extern "C" void kernel_launch(void* const* d_in, const int* in_sizes, int n_in,
                              void* d_out, int out_size) {
    const float* x     = (const float*)d_in[0];
    const float* gamma = (const float*)d_in[1];
    const float* beta  = (const float*)d_in[2];
    const float* wq    = (const float*)d_in[3];
    const float* bq    = (const float*)d_in[4];
    const float* wk    = (const float*)d_in[5];
    const float* bk    = (const float*)d_in[6];
    const float* wv    = (const float*)d_in[7];
    const float* bv    = (const float*)d_in[8];
    const float* wp    = (const float*)d_in[9];
    const float* bp    = (const float*)d_in[10];
    float* out = (float*)d_out;

    float *h, *q, *k, *v, *o, *s, *wr;
    cudaGetSymbolAddress((void**)&h,  g_h);
    cudaGetSymbolAddress((void**)&q,  g_q);
    cudaGetSymbolAddress((void**)&k,  g_k);
    cudaGetSymbolAddress((void**)&v,  g_v);
    cudaGetSymbolAddress((void**)&o,  g_o);
    cudaGetSymbolAddress((void**)&s,  g_s);
    cudaGetSymbolAddress((void**)&wr, g_w);

    cudaFuncSetAttribute(mma_gemm<false, true>,  cudaFuncAttributeMaxDynamicSharedMemorySize, SMEM_BYTES);
    cudaFuncSetAttribute(mma_gemm<false, false>, cudaFuncAttributeMaxDynamicSharedMemorySize, SMEM_BYTES);
    cudaFuncSetAttribute(mma_gemm<true,  false>, cudaFuncAttributeMaxDynamicSharedMemorySize, SMEM_BYTES);

    const long sQK = (long)HW_ * C_;
    const long sS  = (long)HW_ * HW_;
    const float* wqR = wr;
    const float* wkR = wr + (size_t)C_ * C_;
    const float* wvR = wr + (size_t)2 * C_ * C_;
    const float* wpR = wr + (size_t)3 * C_ * C_;

    // 0) round weights to tf32
    wround<<<dim3(256, 4), 256>>>(wq, wk, wv, wp);

    // 1) GroupNorm (h = tf32-rounded)
    gn_part<<<dim3(B_ * G_, 8), 256>>>(x);
    gn_red<<<1, B_ * G_>>>();
    gn_apply<<<TOK_ * C_ / 4 / 256, 256>>>(x, gamma, beta);

    // 2) Q,K,V projections: h[8192,512] @ W[512,512]  (NN, outputs rounded)
    mma_gemm<false, true><<<dim3(4, 64, 1), 256, SMEM_BYTES>>>(h, wqR, bq, nullptr, q, TOK_, C_, C_, 0, 0, 0, 1.f);
    mma_gemm<false, true><<<dim3(4, 64, 1), 256, SMEM_BYTES>>>(h, wkR, bk, nullptr, k, TOK_, C_, C_, 0, 0, 0, 1.f);
    mma_gemm<false, true><<<dim3(4, 64, 1), 256, SMEM_BYTES>>>(h, wvR, bv, nullptr, v, TOK_, C_, C_, 0, 0, 0, 1.f);

    // 3) S = scale * Q @ K^T  (NT), per batch 4096x4096x512
    mma_gemm<true, false><<<dim3(32, 32, B_), 256, SMEM_BYTES>>>(q, k, nullptr, nullptr, s,
                                                                 HW_, HW_, C_, sQK, sQK, sS, SCALE_);
    // 4) softmax (P rounded to tf32)
    softmax_rows<<<B_ * HW_, 512>>>(s);

    // 5) O = P @ V (NN), per batch 4096x512x4096, output rounded
    mma_gemm<false, true><<<dim3(4, 32, B_), 256, SMEM_BYTES>>>(s, v, nullptr, nullptr, o,
                                                                HW_, C_, HW_, sS, sQK, sQK, 1.f);

    // 6) out = x + O @ Wp + bp (NN)
    mma_gemm<false, false><<<dim3(4, 64, 1), 256, SMEM_BYTES>>>(o, wpR, bp, x, out, TOK_, C_, C_, 0, 0, 0, 1.f);
}

// round 4
// speedup vs baseline: 4.7564x; 1.6870x over previous
#include <cuda_runtime.h>
#include <cuda_fp16.h>
#include <cstdint>
#include <math.h>

#define B_    2
#define HW_   4096
#define C_    512
#define TOK_  8192
#define G_    32
#define CPG_  16
#define EPS_  1e-5f
#define SCALE_ 0.04419417382415922f   // 1/sqrt(512)

// ---------------- scratch (device globals, half precision) ------------------
__device__ __half g_h[TOK_ * C_];
__device__ __half g_q[TOK_ * C_];
__device__ __half g_k[TOK_ * C_];
__device__ __half g_v[TOK_ * C_];
__device__ __half g_vt[TOK_ * C_];                 // V^T per batch [C][HW]
__device__ __half g_o[TOK_ * C_];
__device__ __half g_wt[4 * C_ * C_];               // W^T in half [N][K]
__device__ __half g_s[(size_t)B_ * HW_ * HW_];     // 64 MB scores/probs
__device__ float2 g_part[B_ * G_][8];
__device__ float g_mean[B_ * G_];
__device__ float g_rstd[B_ * G_];

// ---------------- helpers ---------------------------------------------------
__device__ __forceinline__ uint32_t smem_u32(const void* p) {
    uint32_t a;
    asm("{ .reg .u64 t; cvta.to.shared.u64 t, %1; cvt.u32.u64 %0, t; }" : "=r"(a) : "l"(p));
    return a;
}
__device__ __forceinline__ void cp16(uint32_t dst, const void* src) {
    asm volatile("cp.async.ca.shared.global [%0], [%1], 16;" :: "r"(dst), "l"(src));
}
__device__ __forceinline__ void cp_commit() { asm volatile("cp.async.commit_group;"); }
__device__ __forceinline__ void cp_wait2()  { asm volatile("cp.async.wait_group 2;" ::: "memory"); }

// m16n8k16 fp16 mma, fp32 accumulate in-place
__device__ __forceinline__ void mma16(float* d, const uint32_t* a, const uint32_t* b) {
    asm volatile(
        "mma.sync.aligned.m16n8k16.row.col.f32.f16.f16.f32 "
        "{%0,%1,%2,%3}, {%4,%5,%6,%7}, {%8,%9}, {%0,%1,%2,%3};"
        : "+f"(d[0]), "+f"(d[1]), "+f"(d[2]), "+f"(d[3])
        : "r"(a[0]), "r"(a[1]), "r"(a[2]), "r"(a[3]), "r"(b[0]), "r"(b[1]));
}

#define ROWH      40                        // halves per smem row (32 + 8 pad)
#define OP_WORDS  (128 * ROWH / 2)          // 2560 words per operand per stage
#define STAGE_BYTES (2 * OP_WORDS * 4)      // 20480
#define SMEM_BYTES  (4 * STAGE_BYTES)       // 81920

// ---------------- fp16 tensor-core GEMM (all NT) -----------------------------
// C = alpha * A @ B^T (+bias)(+res).  A [M,K] half rm, B [N,K] half rm.
// HOUT: store half (rounded); else float (+res).
template <bool HOUT>
__global__ __launch_bounds__(256, 2)
void hgemm(const __half* __restrict__ A, const __half* __restrict__ Bm,
           const float* __restrict__ bias, const float* __restrict__ res,
           void* __restrict__ Cout,
           int M, int N, int K, long sA, long sB, long sC, float alpha) {
    extern __shared__ char smraw[];
    A  += (long)blockIdx.z * sA;
    Bm += (long)blockIdx.z * sB;
    const float* R = res ? res + (long)blockIdx.z * sC : nullptr;

    const int tid = threadIdx.x;
    const int lane = tid & 31, w = tid >> 5;
    const int gid = lane >> 2, tig = lane & 3;
    const int m0 = blockIdx.y * 128, n0 = blockIdx.x * 128;
    const int wm = (w >> 2) * 64, wn = (w & 3) * 32;
    const uint32_t sb = smem_u32(smraw);
    const int NKB = K >> 5;                 // K-chunks of 32 halves

    auto stage_load = [&](int st, int kb) {
        const uint32_t abase = sb + (uint32_t)st * STAGE_BYTES;
        const uint32_t bbase = abase + OP_WORDS * 4;
        const long k0 = (long)kb * 32;
        #pragma unroll
        for (int t = 0; t < 2; t++) {
            int c = tid + t * 256;
            int row = c >> 2, jq = c & 3;
            uint32_t doff = (uint32_t)(row * ROWH + jq * 8) * 2;
            cp16(abase + doff, A  + (long)(m0 + row) * K + k0 + jq * 8);
            cp16(bbase + doff, Bm + (long)(n0 + row) * K + k0 + jq * 8);
        }
    };

    float acc[4][4][4] = {};

    stage_load(0, 0); cp_commit();
    stage_load(1, NKB > 1 ? 1 : 0); cp_commit();
    stage_load(2, NKB > 2 ? 2 : NKB - 1); cp_commit();

    for (int kb = 0; kb < NKB; kb++) {
        cp_wait2();
        __syncthreads();
        int nk = kb + 3; if (nk >= NKB) nk = NKB - 1;
        stage_load((kb + 3) & 3, nk); cp_commit();

        const uint32_t* As = (const uint32_t*)(smraw + (kb & 3) * STAGE_BYTES);
        const uint32_t* Bs = As + OP_WORDS;
        #pragma unroll
        for (int s = 0; s < 2; s++) {        // two K=16 steps
            const int ko = s * 8 + tig;
            uint32_t a[4][4], b[4][2];
            #pragma unroll
            for (int i = 0; i < 4; i++) {
                int r0 = (wm + 16 * i + gid) * (ROWH / 2) + ko;
                a[i][0] = As[r0];
                a[i][1] = As[r0 + 8 * (ROWH / 2)];
                a[i][2] = As[r0 + 4];
                a[i][3] = As[r0 + 8 * (ROWH / 2) + 4];
            }
            #pragma unroll
            for (int j = 0; j < 4; j++) {
                int rb = (wn + 8 * j + gid) * (ROWH / 2) + ko;
                b[j][0] = Bs[rb];
                b[j][1] = Bs[rb + 4];
            }
            #pragma unroll
            for (int i = 0; i < 4; i++)
                #pragma unroll
                for (int j = 0; j < 4; j++)
                    mma16(acc[i][j], a[i], b[j]);
        }
    }

    // --- epilogue ------------------------------------------------------------
    #pragma unroll
    for (int i = 0; i < 4; i++) {
        #pragma unroll
        for (int j = 0; j < 4; j++) {
            const int m = m0 + wm + 16 * i + gid;
            const int n = n0 + wn + 8 * j + 2 * tig;
            float2 bv = make_float2(0.f, 0.f);
            if (bias) bv = *(const float2*)(bias + n);
            float2 v0, v1;
            v0.x = acc[i][j][0] * alpha + bv.x;
            v0.y = acc[i][j][1] * alpha + bv.y;
            v1.x = acc[i][j][2] * alpha + bv.x;
            v1.y = acc[i][j][3] * alpha + bv.y;
            if (HOUT) {
                __half* Ch = (__half*)Cout + (long)blockIdx.z * sC;
                *(__half2*)(Ch + (long)m * N + n)       = __floats2half2_rn(v0.x, v0.y);
                *(__half2*)(Ch + (long)(m + 8) * N + n) = __floats2half2_rn(v1.x, v1.y);
            } else {
                float* Cf = (float*)Cout + (long)blockIdx.z * sC;
                long o0 = (long)m * N + n, o1 = (long)(m + 8) * N + n;
                if (R) {
                    float2 r0 = *(const float2*)(R + o0);
                    float2 r1 = *(const float2*)(R + o1);
                    v0.x += r0.x; v0.y += r0.y; v1.x += r1.x; v1.y += r1.y;
                }
                *(float2*)(Cf + o0) = v0;
                *(float2*)(Cf + o1) = v1;
            }
        }
    }
}

// ---------------- weight transpose fp32 -> half, [K][N] -> [N][K] ------------
__global__ void wtrans(const float* __restrict__ w0, const float* __restrict__ w1,
                       const float* __restrict__ w2, const float* __restrict__ w3) {
    const float* src = blockIdx.z == 0 ? w0 : blockIdx.z == 1 ? w1
                     : blockIdx.z == 2 ? w2 : w3;
    __half* dst = g_wt + (size_t)blockIdx.z * C_ * C_;
    __shared__ float t[32][33];
    int c0 = blockIdx.x * 32, r0 = blockIdx.y * 32;
    for (int i = threadIdx.y; i < 32; i += 8)
        t[i][threadIdx.x] = src[(long)(r0 + i) * C_ + c0 + threadIdx.x];
    __syncthreads();
    for (int i = threadIdx.y; i < 32; i += 8)
        dst[(long)(c0 + i) * C_ + r0 + threadIdx.x] = __float2half_rn(t[threadIdx.x][i]);
}

// ---------------- V transpose half->half per batch: [HW][C] -> [C][HW] -------
__global__ void vtrans(const __half* __restrict__ in, __half* __restrict__ out) {
    in  += (long)blockIdx.z * HW_ * C_;
    out += (long)blockIdx.z * HW_ * C_;
    __shared__ __half t[32][33];
    int c0 = blockIdx.x * 32, r0 = blockIdx.y * 32;
    for (int i = threadIdx.y; i < 32; i += 8)
        t[i][threadIdx.x] = in[(long)(r0 + i) * C_ + c0 + threadIdx.x];
    __syncthreads();
    for (int i = threadIdx.y; i < 32; i += 8)
        out[(long)(c0 + i) * HW_ + r0 + threadIdx.x] = t[threadIdx.x][i];
}

// ---------------- GroupNorm --------------------------------------------------
__global__ void gn_part(const float* __restrict__ x) {
    int bg = blockIdx.x;
    int b = bg >> 5, g = bg & 31;
    const float* base = x + (size_t)b * HW_ * C_ + g * CPG_;
    float s = 0.f, s2 = 0.f;
    for (int t = 0; t < 2; t++) {
        int p = blockIdx.y * 512 + t * 256 + threadIdx.x;
        const float* px = base + (size_t)p * C_;
        #pragma unroll
        for (int c = 0; c < CPG_; c += 4) {
            float4 v = *(const float4*)(px + c);
            s  += v.x + v.y + v.z + v.w;
            s2 += v.x*v.x + v.y*v.y + v.z*v.z + v.w*v.w;
        }
    }
    __shared__ float sh[256], sh2[256];
    sh[threadIdx.x] = s; sh2[threadIdx.x] = s2;
    __syncthreads();
    for (int o = 128; o > 0; o >>= 1) {
        if (threadIdx.x < o) { sh[threadIdx.x] += sh[threadIdx.x+o]; sh2[threadIdx.x] += sh2[threadIdx.x+o]; }
        __syncthreads();
    }
    if (threadIdx.x == 0) g_part[bg][blockIdx.y] = make_float2(sh[0], sh2[0]);
}

__global__ void gn_red() {
    int bg = threadIdx.x;
    float s = 0.f, s2 = 0.f;
    #pragma unroll
    for (int i = 0; i < 8; i++) { float2 p = g_part[bg][i]; s += p.x; s2 += p.y; }
    const float inv_n = 1.f / (float)(HW_ * CPG_);
    float m = s * inv_n;
    float var = s2 * inv_n - m * m;
    g_mean[bg] = m;
    g_rstd[bg] = rsqrtf(var + EPS_);
}

__global__ void gn_apply(const float* __restrict__ x, const float* __restrict__ gamma,
                         const float* __restrict__ beta) {
    size_t i = ((size_t)blockIdx.x * blockDim.x + threadIdx.x) * 4;
    int c = (int)(i % C_);
    int b = (int)(i / ((size_t)HW_ * C_));
    int bg = b * G_ + c / CPG_;
    float m = g_mean[bg], r = g_rstd[bg];
    float4 xv = *(const float4*)(x + i);
    float4 gv = *(const float4*)(gamma + c);
    float4 bv = *(const float4*)(beta + c);
    __half2 h0 = __floats2half2_rn((xv.x - m) * r * gv.x + bv.x,
                                   (xv.y - m) * r * gv.y + bv.y);
    __half2 h1 = __floats2half2_rn((xv.z - m) * r * gv.z + bv.z,
                                   (xv.w - m) * r * gv.w + bv.w);
    uint2 pk = make_uint2(*(uint32_t*)&h0, *(uint32_t*)&h1);
    *(uint2*)(g_h + i) = pk;
}

// ---------------- softmax over 4096 half cols (one row/block) ----------------
__global__ __launch_bounds__(512)
void softmax_rows(__half* __restrict__ S) {
    __half* p = S + (size_t)blockIdx.x * HW_;
    const int t = threadIdx.x, lane = t & 31, w = t >> 5;
    __shared__ float red[16];

    uint4 raw = ((const uint4*)p)[t];
    float2 f[4];
    f[0] = __half22float2(*(__half2*)&raw.x);
    f[1] = __half22float2(*(__half2*)&raw.y);
    f[2] = __half22float2(*(__half2*)&raw.z);
    f[3] = __half22float2(*(__half2*)&raw.w);

    float mx = -1e30f;
    #pragma unroll
    for (int i = 0; i < 4; i++) mx = fmaxf(mx, fmaxf(f[i].x, f[i].y));
    #pragma unroll
    for (int o = 16; o; o >>= 1) mx = fmaxf(mx, __shfl_xor_sync(~0u, mx, o));
    if (lane == 0) red[w] = mx;
    __syncthreads();
    if (w == 0) {
        float tm = red[lane & 15];
        #pragma unroll
        for (int o = 8; o; o >>= 1) tm = fmaxf(tm, __shfl_xor_sync(~0u, tm, o));
        if (lane == 0) red[0] = tm;
    }
    __syncthreads();
    mx = red[0];
    __syncthreads();

    float sum = 0.f;
    #pragma unroll
    for (int i = 0; i < 4; i++) {
        f[i].x = __expf(f[i].x - mx);
        f[i].y = __expf(f[i].y - mx);
        sum += f[i].x + f[i].y;
    }
    #pragma unroll
    for (int o = 16; o; o >>= 1) sum += __shfl_xor_sync(~0u, sum, o);
    if (lane == 0) red[w] = sum;
    __syncthreads();
    if (w == 0) {
        float ts = red[lane & 15];
        #pragma unroll
        for (int o = 8; o; o >>= 1) ts += __shfl_xor_sync(~0u, ts, o);
        if (lane == 0) red[0] = ts;
    }
    __syncthreads();
    const float inv = 1.f / red[0];

    uint4 outp;
    __half2 h;
    h = __floats2half2_rn(f[0].x * inv, f[0].y * inv); outp.x = *(uint32_t*)&h;
    h = __floats2half2_rn(f[1].x * inv, f[1].y * inv); outp.y = *(uint32_t*)&h;
    h = __floats2half2_rn(f[2].x * inv, f[2].y * inv); outp.z = *(uint32_t*)&h;
    h = __floats2half2_rn(f[3].x * inv, f[3].y * inv); outp.w = *(uint32_t*)&h;
    ((uint4*)p)[t] = outp;
}

// ---------------- launch -----------------------------------------------------
extern "C" void kernel_launch(void* const* d_in, const int* in_sizes, int n_in,
                              void* d_out, int out_size) {
    const float* x     = (const float*)d_in[0];
    const float* gamma = (const float*)d_in[1];
    const float* beta  = (const float*)d_in[2];
    const float* wq    = (const float*)d_in[3];
    const float* bq    = (const float*)d_in[4];
    const float* wk    = (const float*)d_in[5];
    const float* bk    = (const float*)d_in[6];
    const float* wv    = (const float*)d_in[7];
    const float* bv    = (const float*)d_in[8];
    const float* wp    = (const float*)d_in[9];
    const float* bp    = (const float*)d_in[10];
    float* out = (float*)d_out;

    __half *h, *q, *k, *v, *vt, *o, *s, *wt;
    cudaGetSymbolAddress((void**)&h,  g_h);
    cudaGetSymbolAddress((void**)&q,  g_q);
    cudaGetSymbolAddress((void**)&k,  g_k);
    cudaGetSymbolAddress((void**)&v,  g_v);
    cudaGetSymbolAddress((void**)&vt, g_vt);
    cudaGetSymbolAddress((void**)&o,  g_o);
    cudaGetSymbolAddress((void**)&s,  g_s);
    cudaGetSymbolAddress((void**)&wt, g_wt);

    cudaFuncSetAttribute(hgemm<true>,  cudaFuncAttributeMaxDynamicSharedMemorySize, SMEM_BYTES);
    cudaFuncSetAttribute(hgemm<false>, cudaFuncAttributeMaxDynamicSharedMemorySize, SMEM_BYTES);

    const long sQK = (long)HW_ * C_;
    const long sS  = (long)HW_ * HW_;
    const __half* wqT = wt;
    const __half* wkT = wt + (size_t)C_ * C_;
    const __half* wvT = wt + (size_t)2 * C_ * C_;
    const __half* wpT = wt + (size_t)3 * C_ * C_;

    dim3 tb(32, 8);

    // 0) weights -> half, transposed to [N][K]
    wtrans<<<dim3(16, 16, 4), tb>>>(wq, wk, wv, wp);

    // 1) GroupNorm -> h (half)
    gn_part<<<dim3(B_ * G_, 8), 256>>>(x);
    gn_red<<<1, B_ * G_>>>();
    gn_apply<<<TOK_ * C_ / 4 / 256, 256>>>(x, gamma, beta);

    // 2) Q,K,V projections (NT, half out)
    hgemm<true><<<dim3(4, 64, 1), 256, SMEM_BYTES>>>(h, wqT, bq, nullptr, q, TOK_, C_, C_, 0, 0, 0, 1.f);
    hgemm<true><<<dim3(4, 64, 1), 256, SMEM_BYTES>>>(h, wkT, bk, nullptr, k, TOK_, C_, C_, 0, 0, 0, 1.f);
    hgemm<true><<<dim3(4, 64, 1), 256, SMEM_BYTES>>>(h, wvT, bv, nullptr, v, TOK_, C_, C_, 0, 0, 0, 1.f);

    // 3) V^T per batch
    vtrans<<<dim3(C_ / 32, HW_ / 32, B_), tb>>>(v, vt);

    // 4) S = scale * Q @ K^T (NT, half out)
    hgemm<true><<<dim3(32, 32, B_), 256, SMEM_BYTES>>>(q, k, nullptr, nullptr, s,
                                                       HW_, HW_, C_, sQK, sQK, sS, SCALE_);
    // 5) softmax (in-place, half)
    softmax_rows<<<B_ * HW_, 512>>>(s);

    // 6) O = P @ V (NT with B=V^T, half out)
    hgemm<true><<<dim3(4, 32, B_), 256, SMEM_BYTES>>>(s, vt, nullptr, nullptr, o,
                                                      HW_, C_, HW_, sS, sQK, sQK, 1.f);

    // 7) out = x + O @ Wp + bp (float out, residual)
    hgemm<false><<<dim3(4, 64, 1), 256, SMEM_BYTES>>>(o, wpT, bp, x, out, TOK_, C_, C_, 0, 0, 0, 1.f);
}

// round 5
// speedup vs baseline: 5.8886x; 1.2380x over previous
#include <cuda_runtime.h>
#include <cuda_fp16.h>
#include <cstdint>
#include <math.h>

#define B_    2
#define HW_   4096
#define C_    512
#define TOK_  8192
#define G_    32
#define CPG_  16
#define EPS_  1e-5f
#define SCALE_ 0.04419417382415922f   // 1/sqrt(512)

// ---------------- scratch (device globals, half precision) ------------------
__device__ __half g_h[TOK_ * C_];
__device__ __half g_q[TOK_ * C_];
__device__ __half g_k[TOK_ * C_];
__device__ __half g_v[TOK_ * C_];
__device__ __half g_vt[TOK_ * C_];                 // V^T per batch [C][HW]
__device__ __half g_o[TOK_ * C_];
__device__ __half g_wt[4 * C_ * C_];               // W^T half [N][K], q,k,v,p
__device__ __half g_s[(size_t)B_ * HW_ * HW_];     // 64 MB scores/probs
__device__ float2 g_part[B_ * G_][8];
__device__ float g_mean[B_ * G_];
__device__ float g_rstd[B_ * G_];

// ---------------- helpers ---------------------------------------------------
__device__ __forceinline__ uint32_t smem_u32(const void* p) {
    uint32_t a;
    asm("{ .reg .u64 t; cvta.to.shared.u64 t, %1; cvt.u32.u64 %0, t; }" : "=r"(a) : "l"(p));
    return a;
}
__device__ __forceinline__ void cp16(uint32_t dst, const void* src) {
    asm volatile("cp.async.ca.shared.global [%0], [%1], 16;" :: "r"(dst), "l"(src));
}
__device__ __forceinline__ void cp_commit() { asm volatile("cp.async.commit_group;"); }
__device__ __forceinline__ void cp_wait2()  { asm volatile("cp.async.wait_group 2;" ::: "memory"); }

__device__ __forceinline__ void ldm_x4(uint32_t* r, uint32_t addr) {
    asm volatile("ldmatrix.sync.aligned.m8n8.x4.shared.b16 {%0,%1,%2,%3}, [%4];"
        : "=r"(r[0]), "=r"(r[1]), "=r"(r[2]), "=r"(r[3]) : "r"(addr));
}
// m16n8k16 fp16 mma, fp32 accumulate in-place
__device__ __forceinline__ void mma16(float* d, const uint32_t* a, const uint32_t* b) {
    asm volatile(
        "mma.sync.aligned.m16n8k16.row.col.f32.f16.f16.f32 "
        "{%0,%1,%2,%3}, {%4,%5,%6,%7}, {%8,%9}, {%0,%1,%2,%3};"
        : "+f"(d[0]), "+f"(d[1]), "+f"(d[2]), "+f"(d[3])
        : "r"(a[0]), "r"(a[1]), "r"(a[2]), "r"(a[3]), "r"(b[0]), "r"(b[1]));
}

#define ROWH      40                        // halves per smem row (32 + 8 pad)
#define OP_WORDS  (128 * ROWH / 2)          // 2560 words per operand per stage
#define STAGE_BYTES (2 * OP_WORDS * 4)      // 20480
#define SMEM_BYTES  (4 * STAGE_BYTES)       // 81920

// ---------------- fp16 tensor-core GEMM (all NT) -----------------------------
// C = alpha * A @ B^T (+bias)(+res).  A [M,K] half rm, B [N,K] half rm.
// MODE 0: half out.  MODE 1: float out + res.  MODE 2: QKV triple (writes
//         g_q/g_k/g_v selected by n-tile; biases b0/b1/b2).
template <int MODE>
__global__ __launch_bounds__(256, 2)
void hgemm(const __half* __restrict__ A, const __half* __restrict__ Bm,
           const float* __restrict__ b0p, const float* __restrict__ b1p,
           const float* __restrict__ b2p, const float* __restrict__ res,
           void* __restrict__ Cout,
           int M, int N, int K, long sA, long sB, long sC, float alpha) {
    extern __shared__ char smraw[];
    A  += (long)blockIdx.z * sA;
    Bm += (long)blockIdx.z * sB;
    const float* R = (MODE == 1 && res) ? res + (long)blockIdx.z * sC : nullptr;

    const int tid = threadIdx.x;
    const int lane = tid & 31, w = tid >> 5;
    const int gid = lane >> 2, tig = lane & 3;
    const int m0 = blockIdx.y * 128, n0 = blockIdx.x * 128;
    const int wm = (w >> 2) * 64, wn = (w & 3) * 32;
    const uint32_t sb = smem_u32(smraw);
    const int NKB = K >> 5;                 // K-chunks of 32 halves

    // ldmatrix lane addresses (bytes, relative to stage base)
    const uint32_t a_rel = ((uint32_t)(wm + (lane & 15)) * ROWH + (uint32_t)(lane >> 4) * 8) * 2;
    const uint32_t b_rel = OP_WORDS * 4 +
        ((uint32_t)(wn + ((lane >> 4) << 3) + (lane & 7)) * ROWH + (uint32_t)((lane >> 3) & 1) * 8) * 2;

    auto stage_load = [&](int st, int kb) {
        const uint32_t abase = sb + (uint32_t)st * STAGE_BYTES;
        const uint32_t bbase = abase + OP_WORDS * 4;
        const long k0 = (long)kb * 32;
        #pragma unroll
        for (int t = 0; t < 2; t++) {
            int c = tid + t * 256;
            int row = c >> 2, jq = c & 3;
            uint32_t doff = (uint32_t)(row * ROWH + jq * 8) * 2;
            cp16(abase + doff, A  + (long)(m0 + row) * K + k0 + jq * 8);
            cp16(bbase + doff, Bm + (long)(n0 + row) * K + k0 + jq * 8);
        }
    };

    float acc[4][4][4] = {};

    stage_load(0, 0); cp_commit();
    stage_load(1, NKB > 1 ? 1 : 0); cp_commit();
    stage_load(2, NKB > 2 ? 2 : NKB - 1); cp_commit();

    for (int kb = 0; kb < NKB; kb++) {
        cp_wait2();
        __syncthreads();
        int nk = kb + 3; if (nk >= NKB) nk = NKB - 1;
        stage_load((kb + 3) & 3, nk); cp_commit();

        const uint32_t st = sb + (uint32_t)(kb & 3) * STAGE_BYTES;
        #pragma unroll
        for (int s = 0; s < 2; s++) {        // two K=16 steps
            uint32_t a[4][4], bb[2][4];
            #pragma unroll
            for (int i = 0; i < 4; i++)
                ldm_x4(a[i], a_rel + st + (uint32_t)i * (16 * ROWH * 2) + s * 32);
            ldm_x4(bb[0], b_rel + st + s * 32);
            ldm_x4(bb[1], b_rel + st + 16 * ROWH * 2 + s * 32);
            #pragma unroll
            for (int i = 0; i < 4; i++) {
                mma16(acc[i][0], a[i], &bb[0][0]);
                mma16(acc[i][1], a[i], &bb[0][2]);
                mma16(acc[i][2], a[i], &bb[1][0]);
                mma16(acc[i][3], a[i], &bb[1][2]);
            }
        }
    }

    // --- epilogue ------------------------------------------------------------
    const float* bias = b0p;
    __half* Cq = nullptr;
    int Nout = N, ncol0 = n0;
    if (MODE == 2) {
        const int tsel = n0 >> 9;                  // 0:q 1:k 2:v
        bias  = tsel == 0 ? b0p : tsel == 1 ? b1p : b2p;
        Cq    = tsel == 0 ? g_q : tsel == 1 ? g_k : g_v;
        Nout  = C_;
        ncol0 = n0 & 511;
        bias += -(n0 & ~511);                      // so bias[n global] works below
    }

    #pragma unroll
    for (int i = 0; i < 4; i++) {
        #pragma unroll
        for (int j = 0; j < 4; j++) {
            const int m = m0 + wm + 16 * i + gid;
            const int nf = wn + 8 * j + 2 * tig;   // within tile
            const int n = (MODE == 2 ? ncol0 : n0) + nf;
            float2 bv = make_float2(0.f, 0.f);
            if (bias) bv = *(const float2*)(bias + n0 + nf);
            float2 v0, v1;
            v0.x = acc[i][j][0] * alpha + bv.x;
            v0.y = acc[i][j][1] * alpha + bv.y;
            v1.x = acc[i][j][2] * alpha + bv.x;
            v1.y = acc[i][j][3] * alpha + bv.y;
            if (MODE == 1) {
                float* Cf = (float*)Cout + (long)blockIdx.z * sC;
                long o0 = (long)m * N + n, o1 = (long)(m + 8) * N + n;
                if (R) {
                    float2 r0 = *(const float2*)(R + o0);
                    float2 r1 = *(const float2*)(R + o1);
                    v0.x += r0.x; v0.y += r0.y; v1.x += r1.x; v1.y += r1.y;
                }
                *(float2*)(Cf + o0) = v0;
                *(float2*)(Cf + o1) = v1;
            } else {
                __half* Ch = (MODE == 2) ? Cq : (__half*)Cout + (long)blockIdx.z * sC;
                *(__half2*)(Ch + (long)m * Nout + n)       = __floats2half2_rn(v0.x, v0.y);
                *(__half2*)(Ch + (long)(m + 8) * Nout + n) = __floats2half2_rn(v1.x, v1.y);
            }
        }
    }
}

// ---------------- weight transpose fp32 -> half, [K][N] -> [N][K] ------------
__global__ void wtrans(const float* __restrict__ w0, const float* __restrict__ w1,
                       const float* __restrict__ w2, const float* __restrict__ w3) {
    const float* src = blockIdx.z == 0 ? w0 : blockIdx.z == 1 ? w1
                     : blockIdx.z == 2 ? w2 : w3;
    __half* dst = g_wt + (size_t)blockIdx.z * C_ * C_;
    __shared__ float t[32][33];
    int c0 = blockIdx.x * 32, r0 = blockIdx.y * 32;
    for (int i = threadIdx.y; i < 32; i += 8)
        t[i][threadIdx.x] = src[(long)(r0 + i) * C_ + c0 + threadIdx.x];
    __syncthreads();
    for (int i = threadIdx.y; i < 32; i += 8)
        dst[(long)(c0 + i) * C_ + r0 + threadIdx.x] = __float2half_rn(t[threadIdx.x][i]);
}

// ---------------- V transpose half->half per batch: [HW][C] -> [C][HW] -------
__global__ void vtrans(const __half* __restrict__ in, __half* __restrict__ out) {
    in  += (long)blockIdx.z * HW_ * C_;
    out += (long)blockIdx.z * HW_ * C_;
    __shared__ __half t[32][33];
    int c0 = blockIdx.x * 32, r0 = blockIdx.y * 32;
    for (int i = threadIdx.y; i < 32; i += 8)
        t[i][threadIdx.x] = in[(long)(r0 + i) * C_ + c0 + threadIdx.x];
    __syncthreads();
    for (int i = threadIdx.y; i < 32; i += 8)
        out[(long)(c0 + i) * HW_ + r0 + threadIdx.x] = t[threadIdx.x][i];
}

// ---------------- GroupNorm --------------------------------------------------
__global__ void gn_part(const float* __restrict__ x) {
    int bg = blockIdx.x;
    int b = bg >> 5, g = bg & 31;
    const float* base = x + (size_t)b * HW_ * C_ + g * CPG_;
    float s = 0.f, s2 = 0.f;
    for (int t = 0; t < 2; t++) {
        int p = blockIdx.y * 512 + t * 256 + threadIdx.x;
        const float* px = base + (size_t)p * C_;
        #pragma unroll
        for (int c = 0; c < CPG_; c += 4) {
            float4 v = *(const float4*)(px + c);
            s  += v.x + v.y + v.z + v.w;
            s2 += v.x*v.x + v.y*v.y + v.z*v.z + v.w*v.w;
        }
    }
    __shared__ float sh[256], sh2[256];
    sh[threadIdx.x] = s; sh2[threadIdx.x] = s2;
    __syncthreads();
    for (int o = 128; o > 0; o >>= 1) {
        if (threadIdx.x < o) { sh[threadIdx.x] += sh[threadIdx.x+o]; sh2[threadIdx.x] += sh2[threadIdx.x+o]; }
        __syncthreads();
    }
    if (threadIdx.x == 0) g_part[bg][blockIdx.y] = make_float2(sh[0], sh2[0]);
}

__global__ void gn_red() {
    int bg = threadIdx.x;
    float s = 0.f, s2 = 0.f;
    #pragma unroll
    for (int i = 0; i < 8; i++) { float2 p = g_part[bg][i]; s += p.x; s2 += p.y; }
    const float inv_n = 1.f / (float)(HW_ * CPG_);
    float m = s * inv_n;
    float var = s2 * inv_n - m * m;
    g_mean[bg] = m;
    g_rstd[bg] = rsqrtf(var + EPS_);
}

__global__ void gn_apply(const float* __restrict__ x, const float* __restrict__ gamma,
                         const float* __restrict__ beta) {
    size_t i = ((size_t)blockIdx.x * blockDim.x + threadIdx.x) * 4;
    int c = (int)(i % C_);
    int b = (int)(i / ((size_t)HW_ * C_));
    int bg = b * G_ + c / CPG_;
    float m = g_mean[bg], r = g_rstd[bg];
    float4 xv = *(const float4*)(x + i);
    float4 gv = *(const float4*)(gamma + c);
    float4 bv = *(const float4*)(beta + c);
    __half2 h0 = __floats2half2_rn((xv.x - m) * r * gv.x + bv.x,
                                   (xv.y - m) * r * gv.y + bv.y);
    __half2 h1 = __floats2half2_rn((xv.z - m) * r * gv.z + bv.z,
                                   (xv.w - m) * r * gv.w + bv.w);
    uint2 pk = make_uint2(*(uint32_t*)&h0, *(uint32_t*)&h1);
    *(uint2*)(g_h + i) = pk;
}

// ---------------- softmax over 4096 half cols (one row/block) ----------------
__global__ __launch_bounds__(512)
void softmax_rows(__half* __restrict__ S) {
    __half* p = S + (size_t)blockIdx.x * HW_;
    const int t = threadIdx.x, lane = t & 31, w = t >> 5;
    __shared__ float red[16];

    uint4 raw = ((const uint4*)p)[t];
    float2 f[4];
    f[0] = __half22float2(*(__half2*)&raw.x);
    f[1] = __half22float2(*(__half2*)&raw.y);
    f[2] = __half22float2(*(__half2*)&raw.z);
    f[3] = __half22float2(*(__half2*)&raw.w);

    float mx = -1e30f;
    #pragma unroll
    for (int i = 0; i < 4; i++) mx = fmaxf(mx, fmaxf(f[i].x, f[i].y));
    #pragma unroll
    for (int o = 16; o; o >>= 1) mx = fmaxf(mx, __shfl_xor_sync(~0u, mx, o));
    if (lane == 0) red[w] = mx;
    __syncthreads();
    if (w == 0) {
        float tm = red[lane & 15];
        #pragma unroll
        for (int o = 8; o; o >>= 1) tm = fmaxf(tm, __shfl_xor_sync(~0u, tm, o));
        if (lane == 0) red[0] = tm;
    }
    __syncthreads();
    mx = red[0];
    __syncthreads();

    float sum = 0.f;
    #pragma unroll
    for (int i = 0; i < 4; i++) {
        f[i].x = __expf(f[i].x - mx);
        f[i].y = __expf(f[i].y - mx);
        sum += f[i].x + f[i].y;
    }
    #pragma unroll
    for (int o = 16; o; o >>= 1) sum += __shfl_xor_sync(~0u, sum, o);
    if (lane == 0) red[w] = sum;
    __syncthreads();
    if (w == 0) {
        float ts = red[lane & 15];
        #pragma unroll
        for (int o = 8; o; o >>= 1) ts += __shfl_xor_sync(~0u, ts, o);
        if (lane == 0) red[0] = ts;
    }
    __syncthreads();
    const float inv = 1.f / red[0];

    uint4 outp;
    __half2 h;
    h = __floats2half2_rn(f[0].x * inv, f[0].y * inv); outp.x = *(uint32_t*)&h;
    h = __floats2half2_rn(f[1].x * inv, f[1].y * inv); outp.y = *(uint32_t*)&h;
    h = __floats2half2_rn(f[2].x * inv, f[2].y * inv); outp.z = *(uint32_t*)&h;
    h = __floats2half2_rn(f[3].x * inv, f[3].y * inv); outp.w = *(uint32_t*)&h;
    ((uint4*)p)[t] = outp;
}

// ---------------- launch -----------------------------------------------------
extern "C" void kernel_launch(void* const* d_in, const int* in_sizes, int n_in,
                              void* d_out, int out_size) {
    const float* x     = (const float*)d_in[0];
    const float* gamma = (const float*)d_in[1];
    const float* beta  = (const float*)d_in[2];
    const float* wq    = (const float*)d_in[3];
    const float* bq    = (const float*)d_in[4];
    const float* wk    = (const float*)d_in[5];
    const float* bk    = (const float*)d_in[6];
    const float* wv    = (const float*)d_in[7];
    const float* bv    = (const float*)d_in[8];
    const float* wp    = (const float*)d_in[9];
    const float* bp    = (const float*)d_in[10];
    float* out = (float*)d_out;

    __half *h, *k, *vt, *o, *s, *wt;
    cudaGetSymbolAddress((void**)&h,  g_h);
    cudaGetSymbolAddress((void**)&k,  g_k);
    cudaGetSymbolAddress((void**)&vt, g_vt);
    cudaGetSymbolAddress((void**)&o,  g_o);
    cudaGetSymbolAddress((void**)&s,  g_s);
    cudaGetSymbolAddress((void**)&wt, g_wt);
    __half *q, *v;
    cudaGetSymbolAddress((void**)&q, g_q);
    cudaGetSymbolAddress((void**)&v, g_v);

    cudaFuncSetAttribute(hgemm<0>, cudaFuncAttributeMaxDynamicSharedMemorySize, SMEM_BYTES);
    cudaFuncSetAttribute(hgemm<1>, cudaFuncAttributeMaxDynamicSharedMemorySize, SMEM_BYTES);
    cudaFuncSetAttribute(hgemm<2>, cudaFuncAttributeMaxDynamicSharedMemorySize, SMEM_BYTES);

    const long sQK = (long)HW_ * C_;
    const long sS  = (long)HW_ * HW_;
    const __half* wpT = wt + (size_t)3 * C_ * C_;

    dim3 tb(32, 8);

    // 0) weights -> half, transposed to [N][K] (q,k,v stacked then p)
    wtrans<<<dim3(16, 16, 4), tb>>>(wq, wk, wv, wp);

    // 1) GroupNorm -> h (half)
    gn_part<<<dim3(B_ * G_, 8), 256>>>(x);
    gn_red<<<1, B_ * G_>>>();
    gn_apply<<<TOK_ * C_ / 4 / 256, 256>>>(x, gamma, beta);

    // 2) fused QKV projection: h[8192,512] @ Wqkv^T[1536,512]
    hgemm<2><<<dim3(12, 64, 1), 256, SMEM_BYTES>>>(h, wt, bq, bk, bv, nullptr, nullptr,
                                                   TOK_, 1536, C_, 0, 0, 0, 1.f);

    // 3) V^T per batch
    vtrans<<<dim3(C_ / 32, HW_ / 32, B_), tb>>>(v, vt);

    // 4) S = scale * Q @ K^T (NT, half out)
    hgemm<0><<<dim3(32, 32, B_), 256, SMEM_BYTES>>>(q, k, nullptr, nullptr, nullptr, nullptr, s,
                                                    HW_, HW_, C_, sQK, sQK, sS, SCALE_);
    // 5) softmax (in-place, half)
    softmax_rows<<<B_ * HW_, 512>>>(s);

    // 6) O = P @ V (NT with B=V^T, half out)
    hgemm<0><<<dim3(4, 32, B_), 256, SMEM_BYTES>>>(s, vt, nullptr, nullptr, nullptr, nullptr, o,
                                                   HW_, C_, HW_, sS, sQK, sQK, 1.f);

    // 7) out = x + O @ Wp + bp (float out, residual)
    hgemm<1><<<dim3(4, 64, 1), 256, SMEM_BYTES>>>(o, wpT, bp, nullptr, nullptr, x, out,
                                                  TOK_, C_, C_, 0, 0, 0, 1.f);
}